// round 5
// baseline (speedup 1.0000x reference)
#include <cuda_runtime.h>
#include <cuda_bf16.h>
#include <cuda_fp16.h>
#include <cstdint>

#define BB 8
#define KN 512
#define QN 128
#define DD 256
#define NEGC (-1000000.0f)

// scratch
__device__ __half g_qproj[BB * QN * DD];                 // [b*128+q][h]     512KB
__device__ __half g_kprojT[BB * (DD / 8) * KN * 8];      // [b][h/8][k][h%8]   2MB
__device__ float  g_atten[BB * QN * KN];                 // [b][q][k]          2MB

__device__ __forceinline__ unsigned int htanh2(unsigned int x) {
    unsigned int y;
    asm("tanh.approx.f16x2 %0, %1;" : "=r"(y) : "r"(x));
    return y;
}
__device__ __forceinline__ unsigned int hadd2u(unsigned int a, unsigned int b) {
    unsigned int r;
    asm("add.f16x2 %0, %1, %2;" : "=r"(r) : "r"(a), "r"(b));
    return r;
}

// ---------------------------------------------------------------------------
// Kernel 1: projection GEMM (fp32 math), epilogue stores fp16.
//   m <  1024 : q_proj row m  -> g_qproj[m][h]            (row-major half)
//   m >= 1024 : k_proj row    -> g_kprojT[b][h/8][k][h%8] (coalesced-k half)
// ---------------------------------------------------------------------------
__global__ __launch_bounds__(256) void proj_kernel(
    const float* __restrict__ queries,
    const float* __restrict__ keys,
    const float* __restrict__ W_hidden)
{
    __shared__ float As[16][68];
    __shared__ float Bs[16][68];

    const int m0 = blockIdx.x * 64;
    const int n0 = blockIdx.y * 64;
    const bool isQ = (m0 < BB * QN);
    const float* A = isQ ? (queries + m0 * DD) : (keys + (m0 - BB * QN) * DD);
    const int off = isQ ? 0 : DD;

    const int tid = threadIdx.x;
    const int tx = tid & 15;
    const int ty = tid >> 4;

    float acc[4][4] = {};

    for (int kb = 0; kb < DD; kb += 16) {
        #pragma unroll
        for (int i = 0; i < 4; i++) {
            int f = tid + i * 256;
            int m = f >> 4, kk = f & 15;
            As[kk][m] = A[m * DD + kb + kk];
        }
        #pragma unroll
        for (int i = 0; i < 4; i++) {
            int f = tid + i * 256;
            int n = f >> 4, kk = f & 15;
            Bs[kk][n] = W_hidden[(n0 + n) * (2 * DD) + off + kb + kk];
        }
        __syncthreads();
        #pragma unroll
        for (int kk = 0; kk < 16; kk++) {
            float a[4], b[4];
            #pragma unroll
            for (int i = 0; i < 4; i++) a[i] = As[kk][ty * 4 + i];
            #pragma unroll
            for (int j = 0; j < 4; j++) b[j] = Bs[kk][tx * 4 + j];
            #pragma unroll
            for (int i = 0; i < 4; i++)
                #pragma unroll
                for (int j = 0; j < 4; j++)
                    acc[i][j] += a[i] * b[j];
        }
        __syncthreads();
    }

    const int h0 = n0 + tx * 4;          // 4 consecutive h, within one 8-chunk
    if (isQ) {
        #pragma unroll
        for (int i = 0; i < 4; i++) {
            int m = m0 + ty * 4 + i;
            __half2* dst = (__half2*)&g_qproj[m * DD + h0];
            dst[0] = __floats2half2_rn(acc[i][0], acc[i][1]);
            dst[1] = __floats2half2_rn(acc[i][2], acc[i][3]);
        }
    } else {
        const int ch  = h0 >> 3;
        const int rem = h0 & 7;          // 0 or 4
        #pragma unroll
        for (int i = 0; i < 4; i++) {
            int kr = m0 - BB * QN + ty * 4 + i;
            int b  = kr >> 9;
            int k  = kr & (KN - 1);
            __half2* dst = (__half2*)&g_kprojT[(((b * 32 + ch) * KN) + k) * 8 + rem];
            dst[0] = __floats2half2_rn(acc[i][0], acc[i][1]);
            dst[1] = __floats2half2_rn(acc[i][2], acc[i][3]);
        }
    }
}

// ---------------------------------------------------------------------------
// Kernel 2: logits (f16x2 tanh) + masked softmax -> g_atten.
// Block = (b, 2 queries). 256 threads, each owns k=tid and k=tid+256.
// ---------------------------------------------------------------------------
__global__ __launch_bounds__(256, 3) void attn_kernel(
    const void* __restrict__ valid_len,
    const float* __restrict__ W_score)
{
    __shared__ uint4 qpu[2][32];         // 2 queries x 256 halves
    __shared__ float ws[DD];
    __shared__ float sl[2][KN];
    __shared__ float red[9];

    const int tid = threadIdx.x;
    const int b  = blockIdx.x >> 6;
    const int q0 = (blockIdx.x & 63) * 2;

    ws[tid] = W_score[tid];
    if (tid < 64) {
        int j = tid >> 5, c = tid & 31;
        qpu[j][c] = ((const uint4*)(g_qproj + (size_t)(b * QN + q0 + j) * DD))[c];
    }

    int vl;
    {
        const int* w32 = (const int*)valid_len;
        bool is64 = ((w32[1] | w32[3] | w32[5] | w32[7]) == 0);
        vl = is64 ? (int)(((const long long*)valid_len)[b]) : w32[b];
    }
    __syncthreads();

    #pragma unroll
    for (int rep = 0; rep < 2; rep++) {
        const int k = tid + rep * 256;
        const uint4* kp = (const uint4*)g_kprojT + (b * 32) * KN + k;  // +c*KN per chunk
        float acc0 = 0.f, acc1 = 0.f;
        #pragma unroll 8
        for (int c = 0; c < 32; c++) {
            uint4 kv  = kp[c * KN];
            uint4 q0v = qpu[0][c];
            uint4 q1v = qpu[1][c];
            const float4 wa = *(const float4*)&ws[c * 8];
            const float4 wb = *(const float4*)&ws[c * 8 + 4];
            #pragma unroll
            for (int p = 0; p < 4; p++) {
                unsigned int kw = (&kv.x)[p];
                float wlo = (p < 2) ? ((p == 0) ? wa.x : wa.z) : ((p == 2) ? wb.x : wb.z);
                float whi = (p < 2) ? ((p == 0) ? wa.y : wa.w) : ((p == 2) ? wb.y : wb.w);
                {
                    unsigned int t = htanh2(hadd2u((&q0v.x)[p], kw));
                    float2 f = __half22float2(*(__half2*)&t);
                    acc0 = fmaf(wlo, f.x, acc0);
                    acc0 = fmaf(whi, f.y, acc0);
                }
                {
                    unsigned int t = htanh2(hadd2u((&q1v.x)[p], kw));
                    float2 f = __half22float2(*(__half2*)&t);
                    acc1 = fmaf(wlo, f.x, acc1);
                    acc1 = fmaf(whi, f.y, acc1);
                }
            }
        }
        const bool valid = (k < vl);
        sl[0][k] = valid ? acc0 : NEGC;
        sl[1][k] = valid ? acc1 : NEGC;
    }
    __syncthreads();

    #pragma unroll
    for (int j = 0; j < 2; j++) {
        float a = sl[j][tid];
        float c = sl[j][tid + 256];
        float m = fmaxf(a, c);
        #pragma unroll
        for (int o = 16; o; o >>= 1)
            m = fmaxf(m, __shfl_xor_sync(0xFFFFFFFFu, m, o));
        if ((tid & 31) == 0) red[tid >> 5] = m;
        __syncthreads();
        if (tid == 0) {
            float mm = red[0];
            #pragma unroll
            for (int i = 1; i < 8; i++) mm = fmaxf(mm, red[i]);
            red[8] = mm;
        }
        __syncthreads();
        m = red[8];
        float e0 = __expf(a - m);
        float e1 = __expf(c - m);
        float s = e0 + e1;
        #pragma unroll
        for (int o = 16; o; o >>= 1)
            s += __shfl_xor_sync(0xFFFFFFFFu, s, o);
        if ((tid & 31) == 0) red[tid >> 5] = s;
        __syncthreads();
        if (tid == 0) {
            float ss = 0.f;
            #pragma unroll
            for (int i = 0; i < 8; i++) ss += red[i];
            red[8] = ss;
        }
        __syncthreads();
        float inv = 1.0f / red[8];
        float* arow = &g_atten[(size_t)(b * QN + q0 + j) * KN];
        arow[tid]       = e0 * inv;
        arow[tid + 256] = e1 * inv;
        __syncthreads();
    }
}

// ---------------------------------------------------------------------------
// Kernel 3: GEMV out[b,q,v] = sum_k atten[b,q,k] * values[b,k,v].
// Block = (b, 16 q, 64 v), 128 threads, thread tile 4q x 2v.
// ---------------------------------------------------------------------------
__global__ __launch_bounds__(128, 8) void gemv_kernel(
    const float* __restrict__ values,
    float* __restrict__ out)
{
    __shared__ float a_sh[16][129];

    const int tid = threadIdx.x;
    const int v0 = blockIdx.x * 64;
    const int qb = blockIdx.y * 16;
    const int b  = blockIdx.z;

    const int qg = tid >> 5;             // 0..3 -> 4 q each
    const int vp = tid & 31;             // 0..31 -> 2 v each

    float acc[4][2] = {};

    for (int kc = 0; kc < 4; kc++) {
        // stage atten tile [16 q][128 k]
        #pragma unroll
        for (int i = 0; i < 4; i++) {
            int idx = tid + i * 128;     // 512 float4 slots
            int q = idx >> 5, c = idx & 31;
            float4 v4 = *(const float4*)&g_atten[(size_t)(b * QN + qb + q) * KN + kc * 128 + c * 4];
            a_sh[q][c * 4 + 0] = v4.x;
            a_sh[q][c * 4 + 1] = v4.y;
            a_sh[q][c * 4 + 2] = v4.z;
            a_sh[q][c * 4 + 3] = v4.w;
        }
        __syncthreads();

        const float* vptr = values + ((size_t)(b * KN + kc * 128)) * DD + v0 + vp * 2;
        #pragma unroll 8
        for (int kk = 0; kk < 128; kk++) {
            float2 vv = *(const float2*)(vptr + (size_t)kk * DD);
            #pragma unroll
            for (int i = 0; i < 4; i++) {
                float a = a_sh[qg * 4 + i][kk];
                acc[i][0] = fmaf(a, vv.x, acc[i][0]);
                acc[i][1] = fmaf(a, vv.y, acc[i][1]);
            }
        }
        __syncthreads();
    }

    #pragma unroll
    for (int i = 0; i < 4; i++) {
        float2* dst = (float2*)&out[(size_t)(b * QN + qb + qg * 4 + i) * DD + v0 + vp * 2];
        *dst = make_float2(acc[i][0], acc[i][1]);
    }
}

extern "C" void kernel_launch(void* const* d_in, const int* in_sizes, int n_in,
                              void* d_out, int out_size)
{
    const float* keys     = (const float*)d_in[0];
    const float* values   = (const float*)d_in[1];
    const float* queries  = (const float*)d_in[2];
    const void*  valid    = d_in[3];
    const float* W_hidden = (const float*)d_in[4];
    const float* W_score  = (const float*)d_in[5];
    float* out = (float*)d_out;

    dim3 g1(80, 4);
    proj_kernel<<<g1, 256>>>(queries, keys, W_hidden);
    attn_kernel<<<BB * (QN / 2), 256>>>(valid, W_score);
    gemv_kernel<<<dim3(4, 8, 8), 128>>>(values, out);
}

// round 7
// speedup vs baseline: 1.2695x; 1.2695x over previous
#include <cuda_runtime.h>
#include <cuda_bf16.h>
#include <cuda_fp16.h>
#include <cstdint>

#define BB 8
#define KN 512
#define QN 128
#define DD 256
#define NEGC (-1000000.0f)

// scratch
__device__ __half g_qproj[BB * QN * DD];                 // [b*128+q][h]     512KB
__device__ __half g_kprojT[BB * (DD / 8) * KN * 8];      // [b][h/8][k][h%8]   2MB
__device__ float  g_atten[BB * QN * KN];                 // [b][q][k]          2MB

__device__ __forceinline__ unsigned int htanh2(unsigned int x) {
    unsigned int y;
    asm("tanh.approx.f16x2 %0, %1;" : "=r"(y) : "r"(x));
    return y;
}
__device__ __forceinline__ unsigned int hadd2u(unsigned int a, unsigned int b) {
    unsigned int r;
    asm("add.f16x2 %0, %1, %2;" : "=r"(r) : "r"(a), "r"(b));
    return r;
}
__device__ __forceinline__ unsigned int packf2(float2 v) {
    __half2 h = __floats2half2_rn(v.x, v.y);
    return *(unsigned int*)&h;
}
__device__ __forceinline__ void mma16816(float c[4],
    unsigned int a0, unsigned int a1, unsigned int a2, unsigned int a3,
    unsigned int b0, unsigned int b1)
{
    asm("mma.sync.aligned.m16n8k16.row.col.f32.f16.f16.f32 "
        "{%0,%1,%2,%3}, {%4,%5,%6,%7}, {%8,%9}, {%0,%1,%2,%3};"
        : "+f"(c[0]), "+f"(c[1]), "+f"(c[2]), "+f"(c[3])
        : "r"(a0), "r"(a1), "r"(a2), "r"(a3), "r"(b0), "r"(b1));
}

// ---------------------------------------------------------------------------
// Kernel 1: projection GEMM on tensor cores (fp16 in, fp32 accum).
// C[m][h] = sum_d A[m][d] * W_hidden[h][off + d]
// Block tile 64m x 128n, 8 warps (warp tile 32x32), no mainloop smem.
// ---------------------------------------------------------------------------
__global__ __launch_bounds__(256) void proj_kernel(
    const float* __restrict__ queries,
    const float* __restrict__ keys,
    const float* __restrict__ W_hidden)
{
    __shared__ __half cs[64][136];       // 272B pitch (16B-aligned rows)

    const int tid  = threadIdx.x;
    const int wid  = tid >> 5;
    const int lane = tid & 31;
    const int m0 = blockIdx.x * 64;      // 80 m-blocks (16 Q, 64 K)
    const int n0 = blockIdx.y * 128;     // 2 n-blocks
    const bool isQ = (m0 < BB * QN);
    const float* A = isQ ? (queries + (size_t)m0 * DD)
                         : (keys + (size_t)(m0 - BB * QN) * DD);
    const int off = isQ ? 0 : DD;

    const int wm = (wid >> 2) * 32;      // 0 / 32
    const int wn = (wid & 3) * 32;       // 0..96
    const int g  = lane >> 2;            // 0..7
    const int kq = (lane & 3) * 2;       // 0,2,4,6

    float c[2][4][4] = {};

    #pragma unroll 4
    for (int k16 = 0; k16 < DD; k16 += 16) {
        unsigned int a[2][4];
        #pragma unroll
        for (int mf = 0; mf < 2; mf++) {
            const float* ap = A + (size_t)(wm + mf * 16 + g) * DD + k16 + kq;
            a[mf][0] = packf2(*(const float2*)(ap));
            a[mf][1] = packf2(*(const float2*)(ap + 8 * DD));
            a[mf][2] = packf2(*(const float2*)(ap + 8));
            a[mf][3] = packf2(*(const float2*)(ap + 8 * DD + 8));
        }
        unsigned int b[4][2];
        #pragma unroll
        for (int nf = 0; nf < 4; nf++) {
            const float* bp = W_hidden + (size_t)(n0 + wn + nf * 8 + g) * (2 * DD) + off + k16 + kq;
            b[nf][0] = packf2(*(const float2*)(bp));
            b[nf][1] = packf2(*(const float2*)(bp + 8));
        }
        #pragma unroll
        for (int mf = 0; mf < 2; mf++)
            #pragma unroll
            for (int nf = 0; nf < 4; nf++)
                mma16816(c[mf][nf], a[mf][0], a[mf][1], a[mf][2], a[mf][3],
                         b[nf][0], b[nf][1]);
    }

    // stage to smem as half
    #pragma unroll
    for (int mf = 0; mf < 2; mf++) {
        int r0 = wm + mf * 16 + g;
        #pragma unroll
        for (int nf = 0; nf < 4; nf++) {
            int col = wn + nf * 8 + (lane & 3) * 2;
            *(__half2*)&cs[r0][col]     = __floats2half2_rn(c[mf][nf][0], c[mf][nf][1]);
            *(__half2*)&cs[r0 + 8][col] = __floats2half2_rn(c[mf][nf][2], c[mf][nf][3]);
        }
    }
    __syncthreads();

    if (isQ) {
        // 64 rows x 128 halves = 1024 x 16B chunks, 4 per thread
        #pragma unroll
        for (int i = 0; i < 4; i++) {
            int id = tid + i * 256;
            int row = id >> 4, seg = id & 15;
            *(uint4*)&g_qproj[(size_t)(m0 + row) * DD + n0 + seg * 8] =
                *(const uint4*)&cs[row][seg * 8];
        }
    } else {
        // 64 k-rows x 16 h-chunks = 1024 x 16B chunks, 4 per thread
        #pragma unroll
        for (int i = 0; i < 4; i++) {
            int id = tid + i * 256;
            int cc = id >> 6, krow = id & 63;
            int krg = m0 - BB * QN + krow;
            int b = krg >> 9, k = krg & (KN - 1);
            *(uint4*)&g_kprojT[(size_t)(((b * 32 + (n0 >> 3) + cc) * KN) + k) * 8] =
                *(const uint4*)&cs[krow][cc * 8];
        }
    }
}

// ---------------------------------------------------------------------------
// Kernel 2: logits (f16x2 tanh) + masked softmax -> g_atten.
// Block = (b, 2 queries). 256 threads, each owns k=tid and k=tid+256.
// ---------------------------------------------------------------------------
__global__ __launch_bounds__(256, 3) void attn_kernel(
    const void* __restrict__ valid_len,
    const float* __restrict__ W_score)
{
    __shared__ uint4 qpu[2][32];         // 2 queries x 256 halves
    __shared__ float ws[DD];
    __shared__ float sl[2][KN];
    __shared__ float red[9];

    const int tid = threadIdx.x;
    const int b  = blockIdx.x >> 6;
    const int q0 = (blockIdx.x & 63) * 2;

    ws[tid] = W_score[tid];
    if (tid < 64) {
        int j = tid >> 5, c = tid & 31;
        qpu[j][c] = ((const uint4*)(g_qproj + (size_t)(b * QN + q0 + j) * DD))[c];
    }

    int vl;
    {
        const int* w32 = (const int*)valid_len;
        bool is64 = ((w32[1] | w32[3] | w32[5] | w32[7]) == 0);
        vl = is64 ? (int)(((const long long*)valid_len)[b]) : w32[b];
    }
    __syncthreads();

    #pragma unroll
    for (int rep = 0; rep < 2; rep++) {
        const int k = tid + rep * 256;
        const uint4* kp = (const uint4*)g_kprojT + (b * 32) * KN + k;  // +c*KN per chunk
        float acc0 = 0.f, acc1 = 0.f;
        #pragma unroll 8
        for (int c = 0; c < 32; c++) {
            uint4 kv  = kp[c * KN];
            uint4 q0v = qpu[0][c];
            uint4 q1v = qpu[1][c];
            const float4 wa = *(const float4*)&ws[c * 8];
            const float4 wb = *(const float4*)&ws[c * 8 + 4];
            #pragma unroll
            for (int p = 0; p < 4; p++) {
                unsigned int kw = (&kv.x)[p];
                float wlo = (p < 2) ? ((p == 0) ? wa.x : wa.z) : ((p == 2) ? wb.x : wb.z);
                float whi = (p < 2) ? ((p == 0) ? wa.y : wa.w) : ((p == 2) ? wb.y : wb.w);
                {
                    unsigned int t = htanh2(hadd2u((&q0v.x)[p], kw));
                    float2 f = __half22float2(*(__half2*)&t);
                    acc0 = fmaf(wlo, f.x, acc0);
                    acc0 = fmaf(whi, f.y, acc0);
                }
                {
                    unsigned int t = htanh2(hadd2u((&q1v.x)[p], kw));
                    float2 f = __half22float2(*(__half2*)&t);
                    acc1 = fmaf(wlo, f.x, acc1);
                    acc1 = fmaf(whi, f.y, acc1);
                }
            }
        }
        const bool valid = (k < vl);
        sl[0][k] = valid ? acc0 : NEGC;
        sl[1][k] = valid ? acc1 : NEGC;
    }
    __syncthreads();

    #pragma unroll
    for (int j = 0; j < 2; j++) {
        float a = sl[j][tid];
        float c = sl[j][tid + 256];
        float m = fmaxf(a, c);
        #pragma unroll
        for (int o = 16; o; o >>= 1)
            m = fmaxf(m, __shfl_xor_sync(0xFFFFFFFFu, m, o));
        if ((tid & 31) == 0) red[tid >> 5] = m;
        __syncthreads();
        if (tid == 0) {
            float mm = red[0];
            #pragma unroll
            for (int i = 1; i < 8; i++) mm = fmaxf(mm, red[i]);
            red[8] = mm;
        }
        __syncthreads();
        m = red[8];
        float e0 = __expf(a - m);
        float e1 = __expf(c - m);
        float s = e0 + e1;
        #pragma unroll
        for (int o = 16; o; o >>= 1)
            s += __shfl_xor_sync(0xFFFFFFFFu, s, o);
        if ((tid & 31) == 0) red[tid >> 5] = s;
        __syncthreads();
        if (tid == 0) {
            float ss = 0.f;
            #pragma unroll
            for (int i = 0; i < 8; i++) ss += red[i];
            red[8] = ss;
        }
        __syncthreads();
        float inv = 1.0f / red[8];
        float* arow = &g_atten[(size_t)(b * QN + q0 + j) * KN];
        arow[tid]       = e0 * inv;
        arow[tid + 256] = e1 * inv;
        __syncthreads();
    }
}

// ---------------------------------------------------------------------------
// Kernel 3: GEMV out[b,q,v] = sum_k atten[b,q,k] * values[b,k,v].
// Block = (b, 16 q, 64 v), 128 threads, thread tile 4q x 2v.
// ---------------------------------------------------------------------------
__global__ __launch_bounds__(128, 8) void gemv_kernel(
    const float* __restrict__ values,
    float* __restrict__ out)
{
    __shared__ float a_sh[16][129];

    const int tid = threadIdx.x;
    const int v0 = blockIdx.x * 64;
    const int qb = blockIdx.y * 16;
    const int b  = blockIdx.z;

    const int qg = tid >> 5;             // 0..3 -> 4 q each
    const int vp = tid & 31;             // 0..31 -> 2 v each

    float acc[4][2] = {};

    for (int kc = 0; kc < 4; kc++) {
        #pragma unroll
        for (int i = 0; i < 4; i++) {
            int idx = tid + i * 128;
            int q = idx >> 5, c = idx & 31;
            float4 v4 = *(const float4*)&g_atten[(size_t)(b * QN + qb + q) * KN + kc * 128 + c * 4];
            a_sh[q][c * 4 + 0] = v4.x;
            a_sh[q][c * 4 + 1] = v4.y;
            a_sh[q][c * 4 + 2] = v4.z;
            a_sh[q][c * 4 + 3] = v4.w;
        }
        __syncthreads();

        const float* vptr = values + ((size_t)(b * KN + kc * 128)) * DD + v0 + vp * 2;
        #pragma unroll 8
        for (int kk = 0; kk < 128; kk++) {
            float2 vv = *(const float2*)(vptr + (size_t)kk * DD);
            #pragma unroll
            for (int i = 0; i < 4; i++) {
                float a = a_sh[qg * 4 + i][kk];
                acc[i][0] = fmaf(a, vv.x, acc[i][0]);
                acc[i][1] = fmaf(a, vv.y, acc[i][1]);
            }
        }
        __syncthreads();
    }

    #pragma unroll
    for (int i = 0; i < 4; i++) {
        float2* dst = (float2*)&out[(size_t)(b * QN + qb + qg * 4 + i) * DD + v0 + vp * 2];
        *dst = make_float2(acc[i][0], acc[i][1]);
    }
}

extern "C" void kernel_launch(void* const* d_in, const int* in_sizes, int n_in,
                              void* d_out, int out_size)
{
    const float* keys     = (const float*)d_in[0];
    const float* values   = (const float*)d_in[1];
    const float* queries  = (const float*)d_in[2];
    const void*  valid    = d_in[3];
    const float* W_hidden = (const float*)d_in[4];
    const float* W_score  = (const float*)d_in[5];
    float* out = (float*)d_out;

    proj_kernel<<<dim3(80, 2), 256>>>(queries, keys, W_hidden);
    attn_kernel<<<BB * (QN / 2), 256>>>(valid, W_score);
    gemv_kernel<<<dim3(4, 8, 8), 128>>>(values, out);
}